// round 11
// baseline (speedup 1.0000x reference)
#include <cuda_runtime.h>
#include <cuda_fp16.h>
#include <cstdint>

// ---------------------------------------------------------------------------
// out[t,o] = sum_i (x[t,i]*scales[i]) * W[o,i]
//   x [32,4096] f32, W [14336,4096] int32 (int8-valued), scales [4096] f32
//   out [32,14336] f32
//
// R11: fp16 HMMA path with DUPLICATION-FREE warp tiling: TILE_M=64, 128 thr,
// 4 warps, each warp = 16 rows x ALL 32 tokens (A tile read once, B x4).
// Cuts SMEM reread 32KB->24KB per 64 rows; LDSM wavefronts were the dominant
// L1 term (R10: L1 70% co-binding, DRAM pinned 67% across 3 and 6 CTAs/SM).
// Depth-1 W reg staging (8 named int4), split-K x2, double buffer,
// 1 barrier/chunk, grid 448 (one balanced wave).
// ---------------------------------------------------------------------------

#define SWZ(off) ((off) ^ (((off) >> 3) & 0x70))

static constexpr int TOKENS = 32;
static constexpr int INF    = 4096;
static constexpr int OUTF   = 14336;
static constexpr int TILE_M = 64;
static constexpr int NTHR   = 128;
static constexpr int KSPLIT = 2;
static constexpr int KHALF  = INF / KSPLIT;     // 2048
static constexpr int KC     = 64;               // K elements per chunk
static constexpr int NITER  = KHALF / KC;       // 32

// per-buffer SMEM layout (bytes)
static constexpr int A_BYTES = TILE_M * 128;        // 8192 (64 rows x 128B, SW128)
static constexpr int X_OFF   = A_BYTES;             // xs tile 32 x 64 fp16 = 4096
static constexpr int BUF_BYTES  = A_BYTES + TOKENS * 128;  // 12288
static constexpr int SMEM_TOTAL = 2 * BUF_BYTES;           // 24576

// fp16 scaled activations (built by prep kernel)
__device__ __half g_xs[TOKENS * INF];

// ---------------- helpers ----------------
__device__ __forceinline__ uint32_t smem_u32(const void* p) {
    uint32_t a;
    asm("{ .reg .u64 t; cvta.to.shared.u64 t, %1; cvt.u32.u64 %0, t; }"
        : "=r"(a) : "l"(p));
    return a;
}

__device__ __forceinline__ void sts128(uint32_t addr, uint32_t r0, uint32_t r1,
                                       uint32_t r2, uint32_t r3) {
    asm volatile("st.shared.v4.b32 [%0], {%1, %2, %3, %4};"
                 :: "r"(addr), "r"(r0), "r"(r1), "r"(r2), "r"(r3) : "memory");
}

__device__ __forceinline__ void cp16(uint32_t dst, const void* src) {
    asm volatile("cp.async.cg.shared.global [%0], [%1], 16;"
                 :: "r"(dst), "l"(src) : "memory");
}
__device__ __forceinline__ void cp_commit() {
    asm volatile("cp.async.commit_group;" ::: "memory");
}
__device__ __forceinline__ void cp_wait0() {
    asm volatile("cp.async.wait_group 0;" ::: "memory");
}

// pack two ints (|v|<=127, exact in fp16) -> half2 bits
__device__ __forceinline__ uint32_t packhf(int a, int b) {
    __half2 h = __floats2half2_rn((float)a, (float)b);
    return *reinterpret_cast<uint32_t*>(&h);
}

__device__ __forceinline__ void ldsm_x4(uint32_t addr, uint32_t& r0, uint32_t& r1,
                                        uint32_t& r2, uint32_t& r3) {
    asm volatile("ldmatrix.sync.aligned.m8n8.x4.shared.b16 {%0,%1,%2,%3}, [%4];"
                 : "=r"(r0), "=r"(r1), "=r"(r2), "=r"(r3) : "r"(addr));
}

__device__ __forceinline__ void mma_16816(float* d, const uint32_t* a, const uint32_t* b) {
    asm volatile(
        "mma.sync.aligned.m16n8k16.row.col.f32.f16.f16.f32 "
        "{%0,%1,%2,%3}, {%4,%5,%6,%7}, {%8,%9}, {%0,%1,%2,%3};"
        : "+f"(d[0]), "+f"(d[1]), "+f"(d[2]), "+f"(d[3])
        : "r"(a[0]), "r"(a[1]), "r"(a[2]), "r"(a[3]), "r"(b[0]), "r"(b[1]));
}

// ---------------- prep: xs = fp16(x*scales) + zero the output ----------------
static constexpr int OUT_ELEMS = TOKENS * OUTF;        // 458752
static constexpr int OUT_VEC4  = OUT_ELEMS / 4;        // 114688

__global__ void prep_kernel(const float* __restrict__ x, const float* __restrict__ s,
                            float4* __restrict__ out4) {
    int i = blockIdx.x * blockDim.x + threadIdx.x;
    if (i < TOKENS * INF) {
        int k = i & (INF - 1);
        g_xs[i] = __float2half_rn(x[i] * s[k]);
    }
    if (i < OUT_VEC4) {
        out4[i] = make_float4(0.f, 0.f, 0.f, 0.f);
    }
}

// ---------------- main GEMM ----------------
__global__ void __launch_bounds__(NTHR, 4)
qgemm_kernel(const int* __restrict__ W, float* __restrict__ out) {
    __shared__ __align__(1024) char smem[SMEM_TOTAL];
    const uint32_t sb = smem_u32(smem);
    const int tid = threadIdx.x;
    const int lane = tid & 31;
    const int wid = tid >> 5;      // 0..3 -> row group (16 rows each)

    const int tile = blockIdx.x >> 1;
    const int kbase = (blockIdx.x & 1) * KHALF;
    const int row_base = tile * TILE_M;

    // ---- W producer: 4 granules (16B fp16 each = 2 int4 of source) ----
    // granule p: row m0 + 16p, col granule c0 (16B fp16 = 8 weights = 32B src)
    const int m0 = tid >> 3;             // 0..15
    const int c0 = tid & 7;              // 0..7
    const char* wpB = (const char*)(W + (size_t)(row_base + m0) * INF + kbase + c0 * 8);
    const uint32_t wsts0 = SWZ(m0 * 128 + c0 * 16);     // +p*2048 per granule (exact)
    static constexpr int WROWSTEP = 16 * INF * 4;       // bytes between granules p

    // ---- xs producer: 2 granules of 8 fp16 per thread ----
    const char* xpA;
    const char* xpB;
    uint32_t xstsA, xstsB;
    {
        int i0 = tid;            // 0..127 -> tokens 0..15
        int i1 = tid + NTHR;     // 128..255 -> tokens 16..31
        int t0 = i0 >> 3, cc0 = i0 & 7;
        int t1 = i1 >> 3, cc1 = i1 & 7;
        xpA = (const char*)(g_xs + t0 * INF + kbase + cc0 * 8);
        xpB = (const char*)(g_xs + t1 * INF + kbase + cc1 * 8);
        xstsA = X_OFF + SWZ(t0 * 128 + cc0 * 16);
        xstsB = X_OFF + SWZ(t1 * 128 + cc1 * 16);
    }

    // ---- ldmatrix lane geometry ----
    const int rowA   = wid * 16 + (lane & 7) + (lane & 8);
    const int aCsel  = (lane & 16);             // +8 fp16 cols -> +16 bytes
    const int tokBlo = (lane & 7) + ((lane & 16) >> 1);     // tokens 0-15 group
    const int bCsel  = (lane & 8) * 2;          // +16 bytes for k+8 tile
    const int aOff   = rowA * 128 + aCsel;
    const int bOffLo = tokBlo * 128 + bCsel;
    const int bOffHi = bOffLo + 16 * 128;       // tokens 16-31

    float acc[4][4];
#pragma unroll
    for (int n = 0; n < 4; n++)
#pragma unroll
        for (int r = 0; r < 4; r++) acc[n][r] = 0.0f;

    // depth-1 W staging: 8 named int4, constant indices only
    int4 w[8];

    // ---- prologue: W chunk 0 -> regs; xs chunk 0 -> cp.async ----
#pragma unroll
    for (int p = 0; p < 4; p++) {
        w[2 * p]     = *(const int4*)(wpB + p * WROWSTEP);
        w[2 * p + 1] = *(const int4*)(wpB + p * WROWSTEP + 16);
    }
    wpB += KC * 4;   // next chunk (bytes)

    cp16(sb + xstsA, xpA); xpA += KC * 2;
    cp16(sb + xstsB, xpB); xpB += KC * 2;
    cp_commit();

#pragma unroll 1
    for (int it = 0; it < NITER; ++it) {
        const uint32_t bufb = sb + (it & 1) * BUF_BYTES;

        // ---- convert + store W tile (readers proven done via sync(it-1)) ----
#pragma unroll
        for (int p = 0; p < 4; p++) {
            int4 u = w[2 * p], v = w[2 * p + 1];
            sts128(bufb + wsts0 + p * 2048,
                   packhf(u.x, u.y), packhf(u.z, u.w),
                   packhf(v.x, v.y), packhf(v.z, v.w));
        }

        // ---- refill stage with chunk it+1 (consumed one full period later) ----
        if (it + 1 < NITER) {
#pragma unroll
            for (int p = 0; p < 4; p++) {
                w[2 * p]     = *(const int4*)(wpB + p * WROWSTEP);
                w[2 * p + 1] = *(const int4*)(wpB + p * WROWSTEP + 16);
            }
            wpB += KC * 4;
        }

        cp_wait0();        // xs(it) landed
        __syncthreads();   // tile (it) visible; compute(it-1) done on all warps

        // ---- xs(it+1) cp.async into the other buffer ----
        if (it + 1 < NITER) {
            const uint32_t nb = sb + ((it + 1) & 1) * BUF_BYTES;
            cp16(nb + xstsA, xpA); xpA += KC * 2;
            cp16(nb + xstsB, xpB); xpB += KC * 2;
            cp_commit();
        }

        // ---- compute: 4 k16-steps; per step 1 A-ldsm + 2 B-ldsm + 4 MMA ----
#pragma unroll
        for (int ks = 0; ks < 4; ks++) {
            uint32_t a[4], bl[4], bh[4];
            const int kb = ks * 32;
            ldsm_x4(bufb + SWZ(aOff + kb), a[0], a[1], a[2], a[3]);
            ldsm_x4(bufb + X_OFF + SWZ(bOffLo + kb), bl[0], bl[1], bl[2], bl[3]);
            mma_16816(acc[0], a, bl + 0);
            mma_16816(acc[1], a, bl + 2);
            ldsm_x4(bufb + X_OFF + SWZ(bOffHi + kb), bh[0], bh[1], bh[2], bh[3]);
            mma_16816(acc[2], a, bh + 0);
            mma_16816(acc[3], a, bh + 2);
        }
    }

    // ---- epilogue: atomicAdd partials (2 deterministic contributors/elem) ----
    const int g = lane >> 2;
    const int t2 = (lane & 3) * 2;
    const int f0 = row_base + wid * 16 + g;
#pragma unroll
    for (int nt = 0; nt < 4; nt++) {
        const int tok = nt * 8 + t2;
        atomicAdd(&out[(size_t)tok * OUTF + f0],           acc[nt][0]);
        atomicAdd(&out[(size_t)(tok + 1) * OUTF + f0],     acc[nt][1]);
        atomicAdd(&out[(size_t)tok * OUTF + f0 + 8],       acc[nt][2]);
        atomicAdd(&out[(size_t)(tok + 1) * OUTF + f0 + 8], acc[nt][3]);
    }
}

// ---------------- launch ----------------
extern "C" void kernel_launch(void* const* d_in, const int* in_sizes, int n_in,
                              void* d_out, int out_size) {
    const float* x      = (const float*)d_in[0];
    const int*   weight = (const int*)d_in[1];
    const float* scales = (const float*)d_in[2];
    float*       out    = (float*)d_out;
    (void)in_sizes; (void)n_in; (void)out_size;

    prep_kernel<<<(TOKENS * INF + 255) / 256, 256>>>(x, scales, (float4*)out);
    qgemm_kernel<<<(OUTF / TILE_M) * KSPLIT, NTHR>>>(weight, out);
}